// round 2
// baseline (speedup 1.0000x reference)
#include <cuda_runtime.h>
#include <cuda_bf16.h>
#include <math.h>

// Problem constants (fixed by the dataset)
#define MAXN 50000
#define MAXE 800000
#define INC 128
#define OUTC 64

// ---------------- scratch (no allocation allowed) ----------------
__device__ __align__(16) float g_bufA[MAXN * 128];
__device__ __align__(16) float g_bufB[MAXN * 128];
__device__ float g_dinv[MAXN];
__device__ int   g_deg[MAXN];
__device__ int   g_off[MAXN + 1];
__device__ int   g_cur[MAXN];
__device__ int   g_col[MAXE];
__device__ int   g_blksum[64];

// ---------------- CSR build ----------------
__global__ void k_init(int n) {
    int i = blockIdx.x * blockDim.x + threadIdx.x;
    if (i < n) { g_deg[i] = 0; g_cur[i] = 0; }
}

__global__ void k_count(const int* __restrict__ dst, int e) {
    int i = blockIdx.x * blockDim.x + threadIdx.x;
    if (i < e) atomicAdd(&g_deg[dst[i]], 1);
}

// inclusive scan per 1024-block -> g_off[i+1], block totals -> g_blksum
__global__ void k_scanA(int n) {
    __shared__ int sm[1024];
    int i = blockIdx.x * 1024 + threadIdx.x;
    int v = (i < n) ? g_deg[i] : 0;
    sm[threadIdx.x] = v;
    __syncthreads();
    for (int s = 1; s < 1024; s <<= 1) {
        int t = (threadIdx.x >= s) ? sm[threadIdx.x - s] : 0;
        __syncthreads();
        sm[threadIdx.x] += t;
        __syncthreads();
    }
    if (i < n) g_off[i + 1] = sm[threadIdx.x];
    if (threadIdx.x == 1023) g_blksum[blockIdx.x] = sm[1023];
}

__global__ void k_scanB(int nb) {
    if (threadIdx.x == 0 && blockIdx.x == 0) {
        int run = 0;
        for (int b = 0; b < nb; b++) { int t = g_blksum[b]; g_blksum[b] = run; run += t; }
    }
}

__global__ void k_scanC(int n) {
    int i = blockIdx.x * 1024 + threadIdx.x;
    if (i < n) g_off[i + 1] += g_blksum[blockIdx.x];
    if (i == 0) g_off[0] = 0;
}

__global__ void k_dinv(int n) {
    int i = blockIdx.x * blockDim.x + threadIdx.x;
    if (i < n) g_dinv[i] = rsqrtf((float)(g_deg[i] + 1));  // +1 self loop; deg>=1 always
}

__global__ void k_fill(const int* __restrict__ src, const int* __restrict__ dst, int e) {
    int i = blockIdx.x * blockDim.x + threadIdx.x;
    if (i < e) {
        int d = dst[i];
        int p = atomicAdd(&g_cur[d], 1);
        g_col[g_off[d] + p] = src[i];
    }
}

// ---------------- SGEMM: out[M,NC] = A[M,K] @ W[K,NC]  (opt: *dinv[row], +bias[col]) ----------------
template <int K, int NC, bool SCALE, bool BIAS>
__global__ void k_gemm(const float* __restrict__ A, const float* __restrict__ W,
                       const float* __restrict__ bias, float* __restrict__ out, int M) {
    constexpr int BM = 64, BN = 64, BK = 32;
    __shared__ float As[BK][BM + 1];
    __shared__ float Bs[BK][BN];
    int tid = threadIdx.x;
    int row0 = blockIdx.x * BM;
    int col0 = blockIdx.y * BN;
    int tx = tid & 15, ty = tid >> 4;
    float acc[4][4] = {};

    for (int k0 = 0; k0 < K; k0 += BK) {
#pragma unroll
        for (int i = 0; i < 8; i++) {          // A tile 64x32
            int lin = tid + i * 256;
            int r = lin >> 5, c = lin & 31;
            int gr = row0 + r;
            As[c][r] = (gr < M) ? A[gr * K + k0 + c] : 0.f;
        }
#pragma unroll
        for (int i = 0; i < 8; i++) {          // W tile 32x64
            int lin = tid + i * 256;
            int r = lin >> 6, c = lin & 63;
            Bs[r][c] = W[(k0 + r) * NC + col0 + c];
        }
        __syncthreads();
#pragma unroll
        for (int kk = 0; kk < BK; kk++) {
            float a[4], b[4];
#pragma unroll
            for (int i = 0; i < 4; i++) a[i] = As[kk][ty * 4 + i];
#pragma unroll
            for (int j = 0; j < 4; j++) b[j] = Bs[kk][tx * 4 + j];
#pragma unroll
            for (int i = 0; i < 4; i++)
#pragma unroll
                for (int j = 0; j < 4; j++) acc[i][j] += a[i] * b[j];
        }
        __syncthreads();
    }
#pragma unroll
    for (int i = 0; i < 4; i++) {
        int gr = row0 + ty * 4 + i;
        if (gr >= M) continue;
        float sc = SCALE ? g_dinv[gr] : 1.f;
#pragma unroll
        for (int j = 0; j < 4; j++) {
            int gc = col0 + tx * 4 + j;
            float v = acc[i][j] * sc;
            if (BIAS) v += bias[gc];
            out[gr * NC + gc] = v;
        }
    }
}

// ---------------- pull-mode aggregation: out[d] = dinv[d]*(hs[d] + sum_neigh hs[src]) + b ----------------
template <int C, bool RELU>
__global__ void k_agg(const float4* __restrict__ hs, const float* __restrict__ bias,
                      float* __restrict__ out, int n) {
    constexpr int L = C / 4;
    int lane = threadIdx.x;  // 0..L-1
    int node = blockIdx.x * blockDim.y + threadIdx.y;
    if (node >= n) return;
    float4 acc = hs[node * L + lane];  // self loop term
    int b0 = g_off[node], b1 = g_off[node + 1];
    for (int j = b0; j < b1; j++) {
        int s = g_col[j];
        float4 v = hs[s * L + lane];
        acc.x += v.x; acc.y += v.y; acc.z += v.z; acc.w += v.w;
    }
    float di = g_dinv[node];
    float4 bb = reinterpret_cast<const float4*>(bias)[lane];
    float4 o;
    o.x = acc.x * di + bb.x;
    o.y = acc.y * di + bb.y;
    o.z = acc.z * di + bb.z;
    o.w = acc.w * di + bb.w;
    if (RELU) {
        o.x = fmaxf(o.x, 0.f); o.y = fmaxf(o.y, 0.f);
        o.z = fmaxf(o.z, 0.f); o.w = fmaxf(o.w, 0.f);
    }
    reinterpret_cast<float4*>(out)[node * L + lane] = o;
}

// ---------------- reparameterize ----------------
__global__ void k_z(const float* __restrict__ mu, const float* __restrict__ lv,
                    const float* __restrict__ eps, float* __restrict__ z, int sz) {
    int i = blockIdx.x * blockDim.x + threadIdx.x;
    if (i < sz) z[i] = mu[i] + eps[i] * expf(0.5f * lv[i]);
}

extern "C" void kernel_launch(void* const* d_in, const int* in_sizes, int n_in,
                              void* d_out, int out_size) {
    const float* x    = (const float*)d_in[0];
    const int*   ei   = (const int*)d_in[1];
    const float* eps  = (const float*)d_in[2];
    const float* W_e1 = (const float*)d_in[3];
    const float* b_e1 = (const float*)d_in[4];
    const float* W_e2 = (const float*)d_in[5];
    const float* b_e2 = (const float*)d_in[6];
    const float* W_mu = (const float*)d_in[7];
    const float* b_mu = (const float*)d_in[8];
    const float* W_lv = (const float*)d_in[9];
    const float* b_lv = (const float*)d_in[10];
    const float* W_d1 = (const float*)d_in[11];
    const float* b_d1 = (const float*)d_in[12];
    const float* W_d2 = (const float*)d_in[13];
    const float* b_d2 = (const float*)d_in[14];

    int N = in_sizes[0] / INC;
    int E = in_sizes[1] / 2;
    const int* src = ei;
    const int* dst = ei + E;

    float* out    = (float*)d_out;
    float* out_d  = out;                     // [N,128]
    float* out_mu = out + (size_t)N * 128;   // [N,64]
    float* out_lv = out_mu + (size_t)N * 64; // [N,64]

    float* bufA; float* bufB;
    cudaGetSymbolAddress((void**)&bufA, g_bufA);
    cudaGetSymbolAddress((void**)&bufB, g_bufB);

    int nbScan = (N + 1023) / 1024;
    int mBlk = (N + 63) / 64;

    // CSR build + norm
    k_init<<<(N + 255) / 256, 256>>>(N);
    k_count<<<(E + 255) / 256, 256>>>(dst, E);
    k_scanA<<<nbScan, 1024>>>(N);
    k_scanB<<<1, 32>>>(nbScan);
    k_scanC<<<nbScan, 1024>>>(N);
    k_dinv<<<(N + 255) / 256, 256>>>(N);
    k_fill<<<(E + 255) / 256, 256>>>(src, dst, E);

    // encoder conv1: hs0 = (x@We1)*dinv ; h1 = relu(agg + b_e1)
    k_gemm<128, 128, true, false><<<dim3(mBlk, 2), 256>>>(x, W_e1, nullptr, bufA, N);
    k_agg<128, true><<<(N + 7) / 8, dim3(32, 8)>>>((const float4*)bufA, b_e1, bufB, N);

    // encoder conv2: hs1 = (h1@We2)*dinv ; h2 = agg + b_e2
    k_gemm<128, 64, true, false><<<dim3(mBlk, 1), 256>>>(bufB, W_e2, nullptr, bufA, N);
    k_agg<64, false><<<(N + 15) / 16, dim3(16, 16)>>>((const float4*)bufA, b_e2, bufB, N);

    // mu / logvar (straight into output slices)
    k_gemm<64, 64, false, true><<<dim3(mBlk, 1), 256>>>(bufB, W_mu, b_mu, out_mu, N);
    k_gemm<64, 64, false, true><<<dim3(mBlk, 1), 256>>>(bufB, W_lv, b_lv, out_lv, N);

    // z = mu + eps * exp(0.5*logvar)
    k_z<<<(N * 64 + 255) / 256, 256>>>(out_mu, out_lv, eps, bufA, N * 64);

    // decoder conv1: hs2 = (z@Wd1)*dinv ; d1 = relu(agg + b_d1)
    k_gemm<64, 128, true, false><<<dim3(mBlk, 2), 256>>>(bufA, W_d1, nullptr, bufB, N);
    k_agg<128, true><<<(N + 7) / 8, dim3(32, 8)>>>((const float4*)bufB, b_d1, bufA, N);

    // decoder conv2: hs3 = (d1@Wd2)*dinv ; d = agg + b_d2 -> output
    k_gemm<128, 128, true, false><<<dim3(mBlk, 2), 256>>>(bufA, W_d2, nullptr, bufB, N);
    k_agg<128, false><<<(N + 7) / 8, dim3(32, 8)>>>((const float4*)bufB, b_d2, out_d, N);
}

// round 3
// speedup vs baseline: 1.0888x; 1.0888x over previous
#include <cuda_runtime.h>
#include <cuda_bf16.h>
#include <math.h>

#define MAXN 50000
#define MAXE 800000
#define INC 128
#define OUTC 64

typedef unsigned long long u64;

// ---------------- scratch (no allocation allowed) ----------------
__device__ __align__(16) float g_bufA[MAXN * 128];
__device__ __align__(16) float g_bufB[MAXN * 128];
__device__ float g_dinv[MAXN];
__device__ int   g_deg[MAXN];
__device__ int   g_off[MAXN + 1];
__device__ int   g_cur[MAXN];
__device__ int   g_col[MAXE];
__device__ int   g_blksum[64];

// ---------------- f32x2 helpers ----------------
__device__ __forceinline__ u64 pack2(float x, float y) {
    u64 r; asm("mov.b64 %0, {%1, %2};" : "=l"(r) : "f"(x), "f"(y)); return r;
}
__device__ __forceinline__ void fma2(u64& d, u64 a, u64 b) {
    asm("fma.rn.f32x2 %0, %1, %2, %3;" : "=l"(d) : "l"(a), "l"(b), "l"(d));
}
__device__ __forceinline__ float2 unpack2(u64 v) {
    float2 f; asm("mov.b64 {%0, %1}, %2;" : "=f"(f.x), "=f"(f.y) : "l"(v)); return f;
}

// ---------------- CSR build ----------------
__global__ void k_init(int n) {
    int i = blockIdx.x * blockDim.x + threadIdx.x;
    if (i < n) { g_deg[i] = 0; g_cur[i] = 0; }
}

__global__ void k_count(const int* __restrict__ dst, int e) {
    int i = blockIdx.x * blockDim.x + threadIdx.x;
    if (i < e) atomicAdd(&g_deg[dst[i]], 1);
}

__global__ void k_scanA(int n) {
    __shared__ int sm[1024];
    int i = blockIdx.x * 1024 + threadIdx.x;
    int v = (i < n) ? g_deg[i] : 0;
    sm[threadIdx.x] = v;
    __syncthreads();
    for (int s = 1; s < 1024; s <<= 1) {
        int t = (threadIdx.x >= s) ? sm[threadIdx.x - s] : 0;
        __syncthreads();
        sm[threadIdx.x] += t;
        __syncthreads();
    }
    if (i < n) g_off[i + 1] = sm[threadIdx.x];
    if (threadIdx.x == 1023) g_blksum[blockIdx.x] = sm[1023];
}

// parallel exclusive scan of <=64 block sums
__global__ void k_scanB(int nb) {
    __shared__ int sm[64];
    int t = threadIdx.x;
    int v = (t < nb) ? g_blksum[t] : 0;
    sm[t] = v;
    __syncthreads();
    for (int s = 1; s < 64; s <<= 1) {
        int u = (t >= s) ? sm[t - s] : 0;
        __syncthreads();
        sm[t] += u;
        __syncthreads();
    }
    if (t < nb) g_blksum[t] = sm[t] - v;  // exclusive
}

__global__ void k_scanC(int n) {
    int i = blockIdx.x * 1024 + threadIdx.x;
    if (i < n) {
        g_off[i + 1] += g_blksum[blockIdx.x];
        g_dinv[i] = rsqrtf((float)(g_deg[i] + 1));  // +1 self loop
    }
    if (i == 0) g_off[0] = 0;
}

__global__ void k_fill(const int* __restrict__ src, const int* __restrict__ dst, int e) {
    int i = blockIdx.x * blockDim.x + threadIdx.x;
    if (i < e) {
        int d = dst[i];
        int p = atomicAdd(&g_cur[d], 1);
        g_col[g_off[d] + p] = src[i];
    }
}

// ---------------- SGEMM (f32x2): out[M,NC] = A[M,K] @ W[K,NC] ----------------
template <int K, int NC, bool SCALE, bool BIAS, bool RELU>
__global__ void k_gemm(const float* __restrict__ A, const float* __restrict__ W,
                       const float* __restrict__ bias, float* __restrict__ out, int M) {
    constexpr int BM = 64, BN = 64, BK = 32;
    __shared__ float As[BK][BM + 2];
    __shared__ float Bs[BK][BN];
    int tid = threadIdx.x;
    int row0 = blockIdx.x * BM;
    int col0 = blockIdx.y * BN;
    int tx = tid & 15, ty = tid >> 4;
    u64 acc2[4][2];
#pragma unroll
    for (int i = 0; i < 4; i++) { acc2[i][0] = 0ull; acc2[i][1] = 0ull; }

    for (int k0 = 0; k0 < K; k0 += BK) {
#pragma unroll
        for (int i = 0; i < 8; i++) {          // A tile 64x32 (transposed into As)
            int lin = tid + i * 256;
            int r = lin >> 5, c = lin & 31;
            int gr = row0 + r;
            As[c][r] = (gr < M) ? A[gr * K + k0 + c] : 0.f;
        }
#pragma unroll
        for (int i = 0; i < 8; i++) {          // W tile 32x64
            int lin = tid + i * 256;
            int r = lin >> 6, c = lin & 63;
            Bs[r][c] = W[(k0 + r) * NC + col0 + c];
        }
        __syncthreads();
#pragma unroll
        for (int kk = 0; kk < BK; kk++) {
            u64 b0 = *reinterpret_cast<const u64*>(&Bs[kk][tx * 4]);
            u64 b1 = *reinterpret_cast<const u64*>(&Bs[kk][tx * 4 + 2]);
#pragma unroll
            for (int i = 0; i < 4; i++) {
                float av = As[kk][ty * 4 + i];
                u64 ap = pack2(av, av);
                fma2(acc2[i][0], ap, b0);
                fma2(acc2[i][1], ap, b1);
            }
        }
        __syncthreads();
    }
    float4 bb;
    if (BIAS) bb = *reinterpret_cast<const float4*>(&bias[col0 + tx * 4]);
#pragma unroll
    for (int i = 0; i < 4; i++) {
        int gr = row0 + ty * 4 + i;
        if (gr >= M) continue;
        float2 c01 = unpack2(acc2[i][0]);
        float2 c23 = unpack2(acc2[i][1]);
        float sc = SCALE ? g_dinv[gr] : 1.f;
        float4 v;
        v.x = c01.x * sc; v.y = c01.y * sc; v.z = c23.x * sc; v.w = c23.y * sc;
        if (BIAS) { v.x += bb.x; v.y += bb.y; v.z += bb.z; v.w += bb.w; }
        if (RELU) {
            v.x = fmaxf(v.x, 0.f); v.y = fmaxf(v.y, 0.f);
            v.z = fmaxf(v.z, 0.f); v.w = fmaxf(v.w, 0.f);
        }
        *reinterpret_cast<float4*>(&out[gr * NC + col0 + tx * 4]) = v;
    }
}

// ---------------- fused mu/logvar/z kernel: h2[M,64] @ {W_mu,W_lv} ----------------
// writes out_mu, out_lv, and zs = (mu + eps*exp(0.5*lv)) * dinv  -> zbuf
__global__ void k_mulvz(const float* __restrict__ A,
                        const float* __restrict__ Wm, const float* __restrict__ bm,
                        const float* __restrict__ Wl, const float* __restrict__ bl,
                        const float* __restrict__ eps,
                        float* __restrict__ out_mu, float* __restrict__ out_lv,
                        float* __restrict__ zbuf, int M) {
    constexpr int K = 64, NC = 64, BM = 64, BK = 32;
    __shared__ float As[BK][BM + 2];
    __shared__ float Ms[BK][NC];
    __shared__ float Ls[BK][NC];
    int tid = threadIdx.x;
    int row0 = blockIdx.x * BM;
    int tx = tid & 15, ty = tid >> 4;
    u64 am[4][2], al[4][2];
#pragma unroll
    for (int i = 0; i < 4; i++) { am[i][0]=0; am[i][1]=0; al[i][0]=0; al[i][1]=0; }

    for (int k0 = 0; k0 < K; k0 += BK) {
#pragma unroll
        for (int i = 0; i < 8; i++) {
            int lin = tid + i * 256;
            int r = lin >> 5, c = lin & 31;
            int gr = row0 + r;
            As[c][r] = (gr < M) ? A[gr * K + k0 + c] : 0.f;
        }
#pragma unroll
        for (int i = 0; i < 8; i++) {
            int lin = tid + i * 256;
            int r = lin >> 6, c = lin & 63;
            Ms[r][c] = Wm[(k0 + r) * NC + c];
            Ls[r][c] = Wl[(k0 + r) * NC + c];
        }
        __syncthreads();
#pragma unroll
        for (int kk = 0; kk < BK; kk++) {
            u64 m0 = *reinterpret_cast<const u64*>(&Ms[kk][tx * 4]);
            u64 m1 = *reinterpret_cast<const u64*>(&Ms[kk][tx * 4 + 2]);
            u64 l0 = *reinterpret_cast<const u64*>(&Ls[kk][tx * 4]);
            u64 l1 = *reinterpret_cast<const u64*>(&Ls[kk][tx * 4 + 2]);
#pragma unroll
            for (int i = 0; i < 4; i++) {
                float av = As[kk][ty * 4 + i];
                u64 ap = pack2(av, av);
                fma2(am[i][0], ap, m0);
                fma2(am[i][1], ap, m1);
                fma2(al[i][0], ap, l0);
                fma2(al[i][1], ap, l1);
            }
        }
        __syncthreads();
    }
    float4 bmu = *reinterpret_cast<const float4*>(&bm[tx * 4]);
    float4 blv = *reinterpret_cast<const float4*>(&bl[tx * 4]);
#pragma unroll
    for (int i = 0; i < 4; i++) {
        int gr = row0 + ty * 4 + i;
        if (gr >= M) continue;
        float2 m01 = unpack2(am[i][0]);
        float2 m23 = unpack2(am[i][1]);
        float2 l01 = unpack2(al[i][0]);
        float2 l23 = unpack2(al[i][1]);
        float4 mu, lv;
        mu.x = m01.x + bmu.x; mu.y = m01.y + bmu.y; mu.z = m23.x + bmu.z; mu.w = m23.y + bmu.w;
        lv.x = l01.x + blv.x; lv.y = l01.y + blv.y; lv.z = l23.x + blv.z; lv.w = l23.y + blv.w;
        float4 ep = *reinterpret_cast<const float4*>(&eps[gr * NC + tx * 4]);
        float di = g_dinv[gr];
        float4 z;
        z.x = (mu.x + ep.x * expf(0.5f * lv.x)) * di;
        z.y = (mu.y + ep.y * expf(0.5f * lv.y)) * di;
        z.z = (mu.z + ep.z * expf(0.5f * lv.z)) * di;
        z.w = (mu.w + ep.w * expf(0.5f * lv.w)) * di;
        *reinterpret_cast<float4*>(&out_mu[gr * NC + tx * 4]) = mu;
        *reinterpret_cast<float4*>(&out_lv[gr * NC + tx * 4]) = lv;
        *reinterpret_cast<float4*>(&zbuf[gr * NC + tx * 4]) = z;
    }
}

// ---------------- pull aggregation: out[d] = dinv[d]*(hs[d] + sum_src hs[src]) (+b)(relu) ----------------
template <int C, bool BIAS, bool RELU>
__global__ void k_agg(const float4* __restrict__ hs, const float* __restrict__ bias,
                      float* __restrict__ out, int n) {
    constexpr int L = C / 4;
    int lane = threadIdx.x;  // 0..L-1
    int node = blockIdx.x * blockDim.y + threadIdx.y;
    if (node >= n) return;
    float4 acc = hs[node * L + lane];  // self loop
    int b0 = g_off[node], b1 = g_off[node + 1];
    int j = b0;
    for (; j + 3 < b1; j += 4) {
        int s0 = g_col[j], s1 = g_col[j + 1], s2 = g_col[j + 2], s3 = g_col[j + 3];
        float4 v0 = hs[s0 * L + lane];
        float4 v1 = hs[s1 * L + lane];
        float4 v2 = hs[s2 * L + lane];
        float4 v3 = hs[s3 * L + lane];
        acc.x += (v0.x + v1.x) + (v2.x + v3.x);
        acc.y += (v0.y + v1.y) + (v2.y + v3.y);
        acc.z += (v0.z + v1.z) + (v2.z + v3.z);
        acc.w += (v0.w + v1.w) + (v2.w + v3.w);
    }
    for (; j < b1; j++) {
        int s = g_col[j];
        float4 v = hs[s * L + lane];
        acc.x += v.x; acc.y += v.y; acc.z += v.z; acc.w += v.w;
    }
    float di = g_dinv[node];
    float4 o;
    o.x = acc.x * di; o.y = acc.y * di; o.z = acc.z * di; o.w = acc.w * di;
    if (BIAS) {
        float4 bb = reinterpret_cast<const float4*>(bias)[lane];
        o.x += bb.x; o.y += bb.y; o.z += bb.z; o.w += bb.w;
    }
    if (RELU) {
        o.x = fmaxf(o.x, 0.f); o.y = fmaxf(o.y, 0.f);
        o.z = fmaxf(o.z, 0.f); o.w = fmaxf(o.w, 0.f);
    }
    reinterpret_cast<float4*>(out)[node * L + lane] = o;
}

extern "C" void kernel_launch(void* const* d_in, const int* in_sizes, int n_in,
                              void* d_out, int out_size) {
    const float* x    = (const float*)d_in[0];
    const int*   ei   = (const int*)d_in[1];
    const float* eps  = (const float*)d_in[2];
    const float* W_e1 = (const float*)d_in[3];
    const float* b_e1 = (const float*)d_in[4];
    const float* W_e2 = (const float*)d_in[5];
    const float* b_e2 = (const float*)d_in[6];
    const float* W_mu = (const float*)d_in[7];
    const float* b_mu = (const float*)d_in[8];
    const float* W_lv = (const float*)d_in[9];
    const float* b_lv = (const float*)d_in[10];
    const float* W_d1 = (const float*)d_in[11];
    const float* b_d1 = (const float*)d_in[12];
    const float* W_d2 = (const float*)d_in[13];
    const float* b_d2 = (const float*)d_in[14];

    int N = in_sizes[0] / INC;
    int E = in_sizes[1] / 2;
    const int* src = ei;
    const int* dst = ei + E;

    float* out    = (float*)d_out;
    float* out_d  = out;                     // [N,128]
    float* out_mu = out + (size_t)N * 128;   // [N,64]
    float* out_lv = out_mu + (size_t)N * 64; // [N,64]

    float* bufA; float* bufB;
    cudaGetSymbolAddress((void**)&bufA, g_bufA);
    cudaGetSymbolAddress((void**)&bufB, g_bufB);

    int nbScan = (N + 1023) / 1024;
    int mBlk = (N + 63) / 64;

    // ---- CSR build + norm ----
    k_init<<<(N + 255) / 256, 256>>>(N);
    k_count<<<(E + 255) / 256, 256>>>(dst, E);
    k_scanA<<<nbScan, 1024>>>(N);
    k_scanB<<<1, 64>>>(nbScan);
    k_scanC<<<nbScan, 1024>>>(N);
    k_fill<<<(E + 255) / 256, 256>>>(src, dst, E);

    // ---- encoder conv1: hs = (x@We1)*dinv ; h1 = relu(agg*dinv + b_e1) ----
    k_gemm<128, 128, true, false, false><<<dim3(mBlk, 2), 256>>>(x, W_e1, nullptr, bufA, N);
    k_agg<128, true, true><<<(N + 7) / 8, dim3(32, 8)>>>((const float4*)bufA, b_e1, bufB, N);

    // ---- encoder conv2: hs = (h1@We2)*dinv ; h2 = agg*dinv + b_e2 ----
    k_gemm<128, 64, true, false, false><<<dim3(mBlk, 1), 256>>>(bufB, W_e2, nullptr, bufA, N);
    k_agg<64, true, false><<<(N + 15) / 16, dim3(16, 16)>>>((const float4*)bufA, b_e2, bufB, N);

    // ---- fused mu/logvar/z: zs = (mu + eps*exp(0.5*lv))*dinv -> bufA ----
    k_mulvz<<<mBlk, 256>>>(bufB, W_mu, b_mu, W_lv, b_lv, eps, out_mu, out_lv, bufA, N);

    // ---- decoder conv1 (reordered): t = agg64(zs)*dinv ; d1 = relu(t@Wd1 + b_d1) ----
    k_agg<64, false, false><<<(N + 15) / 16, dim3(16, 16)>>>((const float4*)bufA, nullptr, bufB, N);
    k_gemm<64, 128, false, true, true><<<dim3(mBlk, 2), 256>>>(bufB, W_d1, b_d1, bufA, N);

    // ---- decoder conv2: hs = (d1@Wd2)*dinv ; d = agg*dinv + b_d2 -> out ----
    k_gemm<128, 128, true, false, false><<<dim3(mBlk, 2), 256>>>(bufA, W_d2, nullptr, bufB, N);
    k_agg<128, true, false><<<(N + 7) / 8, dim3(32, 8)>>>((const float4*)bufB, b_d2, out_d, N);
}

// round 5
// speedup vs baseline: 1.1282x; 1.0362x over previous
#include <cuda_runtime.h>
#include <cuda_bf16.h>
#include <cuda_fp16.h>
#include <math.h>

#define MAXN 50000
#define MAXE 800000
#define INC 128

typedef unsigned long long u64;

// ---------------- scratch (no allocation allowed) ----------------
__device__ __align__(16) float g_bufA[MAXN * 128];   // also used as half/u64 storage
__device__ __align__(16) float g_bufB[MAXN * 128];
__device__ float g_dinv[MAXN];
__device__ int   g_deg[MAXN];
__device__ int   g_off[MAXN + 1];
__device__ int   g_col[MAXE];
__device__ int   g_blksum[64];

// ---------------- f32x2 / half helpers ----------------
__device__ __forceinline__ u64 pack2(float x, float y) {
    u64 r; asm("mov.b64 %0, {%1, %2};" : "=l"(r) : "f"(x), "f"(y)); return r;
}
__device__ __forceinline__ void fma2(u64& d, u64 a, u64 b) {
    asm("fma.rn.f32x2 %0, %1, %2, %3;" : "=l"(d) : "l"(a), "l"(b), "l"(d));
}
__device__ __forceinline__ float2 unpack2(u64 v) {
    float2 f; asm("mov.b64 {%0, %1}, %2;" : "=f"(f.x), "=f"(f.y) : "l"(v)); return f;
}
__device__ __forceinline__ float4 h4f(u64 v) {
    __half2 a = reinterpret_cast<__half2*>(&v)[0];
    __half2 b = reinterpret_cast<__half2*>(&v)[1];
    float2 fa = __half22float2(a), fb = __half22float2(b);
    return make_float4(fa.x, fa.y, fb.x, fb.y);
}
__device__ __forceinline__ u64 f4h(float4 v) {
    u64 r;
    reinterpret_cast<__half2*>(&r)[0] = __floats2half2_rn(v.x, v.y);
    reinterpret_cast<__half2*>(&r)[1] = __floats2half2_rn(v.z, v.w);
    return r;
}

// ---------------- CSR build ----------------
__global__ void k_count(const int* __restrict__ dst, int e) {
    int i = blockIdx.x * blockDim.x + threadIdx.x;
    if (i < e) atomicAdd(&g_deg[dst[i]], 1);
}

__global__ void k_scanA(int n) {
    __shared__ int sm[1024];
    int i = blockIdx.x * 1024 + threadIdx.x;
    int v = (i < n) ? g_deg[i] : 0;
    sm[threadIdx.x] = v;
    __syncthreads();
    for (int s = 1; s < 1024; s <<= 1) {
        int t = (threadIdx.x >= s) ? sm[threadIdx.x - s] : 0;
        __syncthreads();
        sm[threadIdx.x] += t;
        __syncthreads();
    }
    if (i < n) g_off[i + 1] = sm[threadIdx.x];
    if (threadIdx.x == 1023) g_blksum[blockIdx.x] = sm[1023];
}

__global__ void k_scanB(int nb) {
    __shared__ int sm[64];
    int t = threadIdx.x;
    int v = (t < nb) ? g_blksum[t] : 0;
    sm[t] = v;
    __syncthreads();
    for (int s = 1; s < 64; s <<= 1) {
        int u = (t >= s) ? sm[t - s] : 0;
        __syncthreads();
        sm[t] += u;
        __syncthreads();
    }
    if (t < nb) g_blksum[t] = sm[t] - v;  // exclusive
}

__global__ void k_scanC(int n) {
    int i = blockIdx.x * 1024 + threadIdx.x;
    if (i < n) {
        g_off[i + 1] += g_blksum[blockIdx.x];
        g_dinv[i] = rsqrtf((float)(g_deg[i] + 1));  // +1 self loop
    }
    if (i == 0) g_off[0] = 0;
}

// claims slots by decrementing g_deg -> leaves g_deg zeroed for next replay
__global__ void k_fill(const int* __restrict__ src, const int* __restrict__ dst, int e) {
    int i = blockIdx.x * blockDim.x + threadIdx.x;
    if (i < e) {
        int d = dst[i];
        int p = atomicSub(&g_deg[d], 1);          // old count
        g_col[g_off[d] + p - 1] = src[i];
    }
}

// ---------------- SGEMM (f32x2): out[M,NC] = A[M,K] @ W[K,NC] ----------------
// OUTH: write fp16 (packed u64 of 4 halves); else fp32 float4
template <int K, int NC, bool OUTH, bool BIAS, bool RELU>
__global__ void k_gemm(const float* __restrict__ A, const float* __restrict__ W,
                       const float* __restrict__ bias, void* __restrict__ outp, int M) {
    constexpr int BM = 64, BN = 64, BK = 32;
    __shared__ float As[BK][BM + 2];
    __shared__ float Bs[BK][BN];
    int tid = threadIdx.x;
    int row0 = blockIdx.x * BM;
    int col0 = blockIdx.y * BN;
    int tx = tid & 15, ty = tid >> 4;
    u64 acc2[4][2];
#pragma unroll
    for (int i = 0; i < 4; i++) { acc2[i][0] = 0ull; acc2[i][1] = 0ull; }

    for (int k0 = 0; k0 < K; k0 += BK) {
#pragma unroll
        for (int i = 0; i < 8; i++) {          // A tile 64x32 (transposed into As)
            int lin = tid + i * 256;
            int r = lin >> 5, c = lin & 31;
            int gr = row0 + r;
            As[c][r] = (gr < M) ? A[gr * K + k0 + c] : 0.f;
        }
#pragma unroll
        for (int i = 0; i < 8; i++) {          // W tile 32x64
            int lin = tid + i * 256;
            int r = lin >> 6, c = lin & 63;
            Bs[r][c] = W[(k0 + r) * NC + col0 + c];
        }
        __syncthreads();
#pragma unroll
        for (int kk = 0; kk < BK; kk++) {
            u64 b0 = *reinterpret_cast<const u64*>(&Bs[kk][tx * 4]);
            u64 b1 = *reinterpret_cast<const u64*>(&Bs[kk][tx * 4 + 2]);
#pragma unroll
            for (int i = 0; i < 4; i++) {
                float av = As[kk][ty * 4 + i];
                u64 ap = pack2(av, av);
                fma2(acc2[i][0], ap, b0);
                fma2(acc2[i][1], ap, b1);
            }
        }
        __syncthreads();
    }
    float4 bb;
    if (BIAS) bb = *reinterpret_cast<const float4*>(&bias[col0 + tx * 4]);
#pragma unroll
    for (int i = 0; i < 4; i++) {
        int gr = row0 + ty * 4 + i;
        if (gr >= M) continue;
        float2 c01 = unpack2(acc2[i][0]);
        float2 c23 = unpack2(acc2[i][1]);
        float4 v = make_float4(c01.x, c01.y, c23.x, c23.y);
        if (BIAS) { v.x += bb.x; v.y += bb.y; v.z += bb.z; v.w += bb.w; }
        if (RELU) {
            v.x = fmaxf(v.x, 0.f); v.y = fmaxf(v.y, 0.f);
            v.z = fmaxf(v.z, 0.f); v.w = fmaxf(v.w, 0.f);
        }
        int cidx = gr * (NC / 4) + (col0 >> 2) + tx;
        if (OUTH) reinterpret_cast<u64*>(outp)[cidx] = f4h(v);
        else      reinterpret_cast<float4*>(outp)[cidx] = v;
    }
}

// ---------------- fused mu/logvar/z: h2[M,64] @ {W_mu, W_lv} ----------------
// writes mu, lv (fp32) and z = mu + eps*exp(0.5*lv) as fp16 (unscaled; agg applies dinv)
__global__ void k_mulvz(const float* __restrict__ A,
                        const float* __restrict__ Wm, const float* __restrict__ bm,
                        const float* __restrict__ Wl, const float* __restrict__ bl,
                        const float* __restrict__ eps,
                        float* __restrict__ out_mu, float* __restrict__ out_lv,
                        u64* __restrict__ zbuf, int M) {
    constexpr int K = 64, NC = 64, BM = 64, BK = 32;
    __shared__ float As[BK][BM + 2];
    __shared__ float Ms[BK][NC];
    __shared__ float Ls[BK][NC];
    int tid = threadIdx.x;
    int row0 = blockIdx.x * BM;
    int tx = tid & 15, ty = tid >> 4;
    u64 am[4][2], al[4][2];
#pragma unroll
    for (int i = 0; i < 4; i++) { am[i][0]=0; am[i][1]=0; al[i][0]=0; al[i][1]=0; }

    for (int k0 = 0; k0 < K; k0 += BK) {
#pragma unroll
        for (int i = 0; i < 8; i++) {
            int lin = tid + i * 256;
            int r = lin >> 5, c = lin & 31;
            int gr = row0 + r;
            As[c][r] = (gr < M) ? A[gr * K + k0 + c] : 0.f;
        }
#pragma unroll
        for (int i = 0; i < 8; i++) {
            int lin = tid + i * 256;
            int r = lin >> 6, c = lin & 63;
            Ms[r][c] = Wm[(k0 + r) * NC + c];
            Ls[r][c] = Wl[(k0 + r) * NC + c];
        }
        __syncthreads();
#pragma unroll
        for (int kk = 0; kk < BK; kk++) {
            u64 m0 = *reinterpret_cast<const u64*>(&Ms[kk][tx * 4]);
            u64 m1 = *reinterpret_cast<const u64*>(&Ms[kk][tx * 4 + 2]);
            u64 l0 = *reinterpret_cast<const u64*>(&Ls[kk][tx * 4]);
            u64 l1 = *reinterpret_cast<const u64*>(&Ls[kk][tx * 4 + 2]);
#pragma unroll
            for (int i = 0; i < 4; i++) {
                float av = As[kk][ty * 4 + i];
                u64 ap = pack2(av, av);
                fma2(am[i][0], ap, m0);
                fma2(am[i][1], ap, m1);
                fma2(al[i][0], ap, l0);
                fma2(al[i][1], ap, l1);
            }
        }
        __syncthreads();
    }
    float4 bmu = *reinterpret_cast<const float4*>(&bm[tx * 4]);
    float4 blv = *reinterpret_cast<const float4*>(&bl[tx * 4]);
#pragma unroll
    for (int i = 0; i < 4; i++) {
        int gr = row0 + ty * 4 + i;
        if (gr >= M) continue;
        float2 m01 = unpack2(am[i][0]);
        float2 m23 = unpack2(am[i][1]);
        float2 l01 = unpack2(al[i][0]);
        float2 l23 = unpack2(al[i][1]);
        float4 mu, lv;
        mu.x = m01.x + bmu.x; mu.y = m01.y + bmu.y; mu.z = m23.x + bmu.z; mu.w = m23.y + bmu.w;
        lv.x = l01.x + blv.x; lv.y = l01.y + blv.y; lv.z = l23.x + blv.z; lv.w = l23.y + blv.w;
        float4 ep = *reinterpret_cast<const float4*>(&eps[gr * NC + tx * 4]);
        float4 z;
        z.x = mu.x + ep.x * expf(0.5f * lv.x);
        z.y = mu.y + ep.y * expf(0.5f * lv.y);
        z.z = mu.z + ep.z * expf(0.5f * lv.z);
        z.w = mu.w + ep.w * expf(0.5f * lv.w);
        *reinterpret_cast<float4*>(&out_mu[gr * NC + tx * 4]) = mu;
        *reinterpret_cast<float4*>(&out_lv[gr * NC + tx * 4]) = lv;
        zbuf[gr * (NC / 4) + tx] = f4h(z);
    }
}

// ---------------- pull aggregation over fp16 features ----------------
// out[d] = dinv[d] * ( hs[d]*dinv[d] + sum_src hs[src]*dinv[src] ) (+bias)(relu)
template <int C, bool BIAS, bool RELU>
__global__ void k_agg(const u64* __restrict__ hs, const float* __restrict__ bias,
                      float* __restrict__ out, int n) {
    constexpr int L = C / 4;          // u64 (4 halves) per row
    int lane = threadIdx.x;           // 0..L-1
    int node = blockIdx.x * blockDim.y + threadIdx.y;
    if (node >= n) return;
    float di = g_dinv[node];
    float4 sv = h4f(hs[(size_t)node * L + lane]);
    float4 acc = make_float4(sv.x * di, sv.y * di, sv.z * di, sv.w * di);
    int b0 = g_off[node], b1 = g_off[node + 1];
    int j = b0;
    for (; j + 3 < b1; j += 4) {
        int s0 = g_col[j], s1 = g_col[j + 1], s2 = g_col[j + 2], s3 = g_col[j + 3];
        float d0 = g_dinv[s0], d1 = g_dinv[s1], d2 = g_dinv[s2], d3 = g_dinv[s3];
        float4 v0 = h4f(hs[(size_t)s0 * L + lane]);
        float4 v1 = h4f(hs[(size_t)s1 * L + lane]);
        float4 v2 = h4f(hs[(size_t)s2 * L + lane]);
        float4 v3 = h4f(hs[(size_t)s3 * L + lane]);
        acc.x += v0.x * d0 + v1.x * d1 + v2.x * d2 + v3.x * d3;
        acc.y += v0.y * d0 + v1.y * d1 + v2.y * d2 + v3.y * d3;
        acc.z += v0.z * d0 + v1.z * d1 + v2.z * d2 + v3.z * d3;
        acc.w += v0.w * d0 + v1.w * d1 + v2.w * d2 + v3.w * d3;
    }
    for (; j < b1; j++) {
        int s = g_col[j];
        float ds = g_dinv[s];
        float4 v = h4f(hs[(size_t)s * L + lane]);
        acc.x += v.x * ds; acc.y += v.y * ds; acc.z += v.z * ds; acc.w += v.w * ds;
    }
    float4 o = make_float4(acc.x * di, acc.y * di, acc.z * di, acc.w * di);
    if (BIAS) {
        float4 bb = reinterpret_cast<const float4*>(bias)[lane];
        o.x += bb.x; o.y += bb.y; o.z += bb.z; o.w += bb.w;
    }
    if (RELU) {
        o.x = fmaxf(o.x, 0.f); o.y = fmaxf(o.y, 0.f);
        o.z = fmaxf(o.z, 0.f); o.w = fmaxf(o.w, 0.f);
    }
    reinterpret_cast<float4*>(out)[(size_t)node * L + lane] = o;
}

extern "C" void kernel_launch(void* const* d_in, const int* in_sizes, int n_in,
                              void* d_out, int out_size) {
    const float* x    = (const float*)d_in[0];
    const int*   ei   = (const int*)d_in[1];
    const float* eps  = (const float*)d_in[2];
    const float* W_e1 = (const float*)d_in[3];
    const float* b_e1 = (const float*)d_in[4];
    const float* W_e2 = (const float*)d_in[5];
    const float* b_e2 = (const float*)d_in[6];
    const float* W_mu = (const float*)d_in[7];
    const float* b_mu = (const float*)d_in[8];
    const float* W_lv = (const float*)d_in[9];
    const float* b_lv = (const float*)d_in[10];
    const float* W_d1 = (const float*)d_in[11];
    const float* b_d1 = (const float*)d_in[12];
    const float* W_d2 = (const float*)d_in[13];
    const float* b_d2 = (const float*)d_in[14];

    int N = in_sizes[0] / INC;
    int E = in_sizes[1] / 2;
    const int* src = ei;
    const int* dst = ei + E;

    float* out    = (float*)d_out;
    float* out_d  = out;                     // [N,128]
    float* out_mu = out + (size_t)N * 128;   // [N,64]
    float* out_lv = out_mu + (size_t)N * 64; // [N,64]

    float* bufA; float* bufB;
    cudaGetSymbolAddress((void**)&bufA, g_bufA);
    cudaGetSymbolAddress((void**)&bufB, g_bufB);
    u64* hA = (u64*)bufA;   // fp16 feature buffer (also reused as fp32 later)
    u64* hB = (u64*)bufB;

    static cudaStream_t s2 = nullptr;
    static cudaEvent_t evF = nullptr, evJ = nullptr;
    if (!s2) {
        cudaStreamCreateWithFlags(&s2, cudaStreamNonBlocking);
        cudaEventCreateWithFlags(&evF, cudaEventDisableTiming);
        cudaEventCreateWithFlags(&evJ, cudaEventDisableTiming);
    }

    int nbScan = (N + 1023) / 1024;
    int mBlk = (N + 63) / 64;

    // ---- CSR build on side stream (overlaps e1 GEMM) ----
    cudaEventRecord(evF, 0);
    cudaStreamWaitEvent(s2, evF, 0);
    k_count<<<(E + 255) / 256, 256, 0, s2>>>(dst, E);
    k_scanA<<<nbScan, 1024, 0, s2>>>(N);
    k_scanB<<<1, 64, 0, s2>>>(nbScan);
    k_scanC<<<nbScan, 1024, 0, s2>>>(N);
    k_fill<<<(E + 255) / 256, 256, 0, s2>>>(src, dst, E);
    cudaEventRecord(evJ, s2);

    // ---- encoder conv1 GEMM (independent of CSR): hs = x@W_e1 -> fp16 hA ----
    k_gemm<128, 128, true, false, false><<<dim3(mBlk, 2), 256>>>(x, W_e1, nullptr, hA, N);

    cudaStreamWaitEvent(0, evJ, 0);   // CSR ready

    // ---- agg e1: h1 = relu(Â hs + b_e1) -> fp32 bufB ----
    k_agg<128, true, true><<<(N + 7) / 8, dim3(32, 8)>>>(hA, b_e1, bufB, N);

    // ---- encoder conv2: hs = h1@W_e2 -> fp16 hA ; h2 = Â hs + b_e2 -> fp32 bufB ----
    k_gemm<128, 64, true, false, false><<<dim3(mBlk, 1), 256>>>(bufB, W_e2, nullptr, hA, N);
    k_agg<64, true, false><<<(N + 15) / 16, dim3(16, 16)>>>(hA, b_e2, bufB, N);

    // ---- fused mu/logvar/z: mu,lv -> out ; z -> fp16 hA ----
    k_mulvz<<<mBlk, 256>>>(bufB, W_mu, b_mu, W_lv, b_lv, eps, out_mu, out_lv, hA, N);

    // ---- decoder conv1 (reordered): t = Â z -> fp32 bufB ; d1 = relu(t@W_d1+b) -> fp32 bufA ----
    k_agg<64, false, false><<<(N + 15) / 16, dim3(16, 16)>>>(hA, nullptr, bufB, N);
    k_gemm<64, 128, false, true, true><<<dim3(mBlk, 2), 256>>>(bufB, W_d1, b_d1, bufA, N);

    // ---- decoder conv2: hs = d1@W_d2 -> fp16 hB ; d = Â hs + b_d2 -> out ----
    k_gemm<128, 128, true, false, false><<<dim3(mBlk, 2), 256>>>(bufA, W_d2, nullptr, hB, N);
    k_agg<128, true, false><<<(N + 7) / 8, dim3(32, 8)>>>(hB, b_d2, out_d, N);
}

// round 6
// speedup vs baseline: 1.6968x; 1.5040x over previous
#include <cuda_runtime.h>
#include <cuda_bf16.h>
#include <cuda_fp16.h>
#include <math.h>

#define MAXN 50000
#define MAXE 800000
#define INC 128

typedef unsigned long long u64;
typedef unsigned int u32;

// ---------------- scratch (no allocation allowed) ----------------
__device__ __align__(16) float g_bufA[MAXN * 128];
__device__ __align__(16) float g_bufB[MAXN * 128];
__device__ float g_dinv[MAXN];
__device__ int   g_deg[MAXN];
__device__ int   g_off[MAXN + 1];
__device__ int   g_col[MAXE];
__device__ int   g_blksum[64];

// ---------------- helpers ----------------
__device__ __forceinline__ float4 h4f(u64 v) {
    __half2 a = reinterpret_cast<__half2*>(&v)[0];
    __half2 b = reinterpret_cast<__half2*>(&v)[1];
    float2 fa = __half22float2(a), fb = __half22float2(b);
    return make_float4(fa.x, fa.y, fb.x, fb.y);
}
__device__ __forceinline__ u64 f4h(float4 v) {
    u64 r;
    reinterpret_cast<__half2*>(&r)[0] = __floats2half2_rn(v.x, v.y);
    reinterpret_cast<__half2*>(&r)[1] = __floats2half2_rn(v.z, v.w);
    return r;
}

// ---------------- CSR build ----------------
__global__ void k_count(const int* __restrict__ dst, int e) {
    int i = blockIdx.x * blockDim.x + threadIdx.x;
    if (i < e) atomicAdd(&g_deg[dst[i]], 1);
}

__global__ void k_scanA(int n) {
    __shared__ int sm[1024];
    int i = blockIdx.x * 1024 + threadIdx.x;
    int v = (i < n) ? g_deg[i] : 0;
    sm[threadIdx.x] = v;
    __syncthreads();
    for (int s = 1; s < 1024; s <<= 1) {
        int t = (threadIdx.x >= s) ? sm[threadIdx.x - s] : 0;
        __syncthreads();
        sm[threadIdx.x] += t;
        __syncthreads();
    }
    if (i < n) g_off[i + 1] = sm[threadIdx.x];
    if (threadIdx.x == 1023) g_blksum[blockIdx.x] = sm[1023];
}

__global__ void k_scanB(int nb) {
    __shared__ int sm[64];
    int t = threadIdx.x;
    int v = (t < nb) ? g_blksum[t] : 0;
    sm[t] = v;
    __syncthreads();
    for (int s = 1; s < 64; s <<= 1) {
        int u = (t >= s) ? sm[t - s] : 0;
        __syncthreads();
        sm[t] += u;
        __syncthreads();
    }
    if (t < nb) g_blksum[t] = sm[t] - v;  // exclusive
}

__global__ void k_scanC(int n) {
    int i = blockIdx.x * 1024 + threadIdx.x;
    if (i < n) {
        g_off[i + 1] += g_blksum[blockIdx.x];
        g_dinv[i] = rsqrtf((float)(g_deg[i] + 1));
    }
    if (i == 0) g_off[0] = 0;
}

__global__ void k_fill(const int* __restrict__ src, const int* __restrict__ dst, int e) {
    int i = blockIdx.x * blockDim.x + threadIdx.x;
    if (i < e) {
        int d = dst[i];
        int p = atomicSub(&g_deg[d], 1);
        g_col[g_off[d] + p - 1] = src[i];
    }
}

// ---------------- tensor-core GEMM: out[M,NC] = A[M,K] @ W[K,NC] ----------------
// BM=128, BN=64, BK=32, 256 threads (8 warps as 4(m) x 2(n)), m16n8k16 HMMA.
// AF16: A is packed fp16 (u64 of 4) else fp32.  MULV: grid.y selects W/W2 -> outp/outp2 (fp32).
// OUTH: write fp16 else fp32.
template <int K, int NC, bool AF16, bool MULV, bool OUTH, bool BIAS, bool RELU>
__global__ void k_mma(const void* __restrict__ Ap,
                      const float* __restrict__ W,  const float* __restrict__ W2,
                      const float* __restrict__ bias, const float* __restrict__ bias2,
                      void* __restrict__ outp, void* __restrict__ outp2, int M) {
    constexpr int BM = 128, BN = 64, BK = 32, PAD = 8;
    __shared__ __half As[BM][BK + PAD];
    __shared__ __half Bs[BN][BK + PAD];

    const int tid = threadIdx.x;
    const int wid = tid >> 5, lane = tid & 31;
    const int warp_m = wid & 3, warp_n = wid >> 2;
    const int g = lane >> 2, tig = lane & 3;
    const int row0 = blockIdx.x * BM;
    const int col0 = blockIdx.y * BN;

    const float* Wp = MULV ? (blockIdx.y ? W2 : W) : W;
    const float* bp = MULV ? (blockIdx.y ? bias2 : bias) : bias;
    const int wstride = MULV ? 64 : NC;
    const int wcol0 = MULV ? 0 : col0;

    float acc[2][4][4];
#pragma unroll
    for (int mt = 0; mt < 2; mt++)
#pragma unroll
        for (int nt = 0; nt < 4; nt++)
#pragma unroll
            for (int i = 0; i < 4; i++) acc[mt][nt][i] = 0.f;

    for (int k0 = 0; k0 < K; k0 += BK) {
        // ---- A tile: 128 rows x 32 halves ----
#pragma unroll
        for (int it = 0; it < 2; it++) {
            int idx = tid + it * 256;            // 0..511
            int r = idx >> 2, ch = idx & 3;      // chunk of 8 halves
            int gr = row0 + r;
            int4 val;
            if (gr < M) {
                if (AF16) {
                    const int4* A16 = (const int4*)Ap;
                    // u64 index gr*(K/4) + k0/4 + ch*2  -> int4 index /2
                    val = A16[((size_t)gr * (K / 4) + (k0 >> 2) + ch * 2) >> 1];
                } else {
                    const float* Af = (const float*)Ap;
                    const float4* p = (const float4*)&Af[(size_t)gr * K + k0 + ch * 8];
                    float4 f0 = p[0], f1 = p[1];
                    __half2* h = (__half2*)&val;
                    h[0] = __floats2half2_rn(f0.x, f0.y);
                    h[1] = __floats2half2_rn(f0.z, f0.w);
                    h[2] = __floats2half2_rn(f1.x, f1.y);
                    h[3] = __floats2half2_rn(f1.z, f1.w);
                }
            } else {
                val = make_int4(0, 0, 0, 0);
            }
            *(int4*)&As[r][ch * 8] = val;
        }
        // ---- B tile: W[k0..k0+31][wcol0..+63] -> Bs[n][k] (transposed) ----
#pragma unroll
        for (int i = 0; i < 8; i++) {
            int lin = tid + i * 256;             // 0..2047
            int kk = lin >> 6, n = lin & 63;
            Bs[n][kk] = __float2half(Wp[(size_t)(k0 + kk) * wstride + wcol0 + n]);
        }
        __syncthreads();

#pragma unroll
        for (int ks = 0; ks < BK; ks += 16) {
            u32 a[2][4], b[4][2];
#pragma unroll
            for (int mt = 0; mt < 2; mt++) {
                int rb = warp_m * 32 + mt * 16 + g;
                a[mt][0] = *(const u32*)&As[rb][ks + 2 * tig];
                a[mt][1] = *(const u32*)&As[rb + 8][ks + 2 * tig];
                a[mt][2] = *(const u32*)&As[rb][ks + 2 * tig + 8];
                a[mt][3] = *(const u32*)&As[rb + 8][ks + 2 * tig + 8];
            }
#pragma unroll
            for (int nt = 0; nt < 4; nt++) {
                int nb = warp_n * 32 + nt * 8 + g;
                b[nt][0] = *(const u32*)&Bs[nb][ks + 2 * tig];
                b[nt][1] = *(const u32*)&Bs[nb][ks + 2 * tig + 8];
            }
#pragma unroll
            for (int mt = 0; mt < 2; mt++)
#pragma unroll
                for (int nt = 0; nt < 4; nt++) {
                    asm volatile(
                        "mma.sync.aligned.m16n8k16.row.col.f32.f16.f16.f32 "
                        "{%0,%1,%2,%3}, {%4,%5,%6,%7}, {%8,%9}, {%0,%1,%2,%3};"
                        : "+f"(acc[mt][nt][0]), "+f"(acc[mt][nt][1]),
                          "+f"(acc[mt][nt][2]), "+f"(acc[mt][nt][3])
                        : "r"(a[mt][0]), "r"(a[mt][1]), "r"(a[mt][2]), "r"(a[mt][3]),
                          "r"(b[nt][0]), "r"(b[nt][1]));
                }
        }
        __syncthreads();
    }

    // ---- epilogue ----
    const int ncout = MULV ? 64 : NC;
    const int outcol0 = MULV ? 0 : col0;
    float* outf = MULV ? (float*)(blockIdx.y ? outp2 : outp) : (float*)outp;
    __half* outh = (__half*)outp;

#pragma unroll
    for (int mt = 0; mt < 2; mt++) {
        int r0 = row0 + warp_m * 32 + mt * 16 + g;
#pragma unroll
        for (int nt = 0; nt < 4; nt++) {
            int gc = outcol0 + warp_n * 32 + nt * 8 + 2 * tig;
            float2 v0 = make_float2(acc[mt][nt][0], acc[mt][nt][1]);   // row r0
            float2 v1 = make_float2(acc[mt][nt][2], acc[mt][nt][3]);   // row r0+8
            if (BIAS) {
                float2 bb = *(const float2*)&bp[gc - (MULV ? 0 : 0)];
                v0.x += bb.x; v0.y += bb.y; v1.x += bb.x; v1.y += bb.y;
            }
            if (RELU) {
                v0.x = fmaxf(v0.x, 0.f); v0.y = fmaxf(v0.y, 0.f);
                v1.x = fmaxf(v1.x, 0.f); v1.y = fmaxf(v1.y, 0.f);
            }
            if (r0 < M) {
                if (OUTH) *(__half2*)&outh[(size_t)r0 * ncout + gc] = __floats2half2_rn(v0.x, v0.y);
                else      *(float2*)&outf[(size_t)r0 * ncout + gc] = v0;
            }
            if (r0 + 8 < M) {
                if (OUTH) *(__half2*)&outh[(size_t)(r0 + 8) * ncout + gc] = __floats2half2_rn(v1.x, v1.y);
                else      *(float2*)&outf[(size_t)(r0 + 8) * ncout + gc] = v1;
            }
        }
    }
}

// ---------------- z = mu + eps * exp(0.5*lv), fp16 out ----------------
__global__ void k_zh(const float4* __restrict__ mu, const float4* __restrict__ lv,
                     const float4* __restrict__ eps, u64* __restrict__ z, int n4) {
    int i = blockIdx.x * blockDim.x + threadIdx.x;
    if (i < n4) {
        float4 m = mu[i], l = lv[i], e = eps[i];
        float4 v;
        v.x = m.x + e.x * expf(0.5f * l.x);
        v.y = m.y + e.y * expf(0.5f * l.y);
        v.z = m.z + e.z * expf(0.5f * l.z);
        v.w = m.w + e.w * expf(0.5f * l.w);
        z[i] = f4h(v);
    }
}

// ---------------- pull aggregation over fp16 features ----------------
// out[d] = dinv[d] * ( hs[d]*dinv[d] + sum_src hs[src]*dinv[src] ) (+bias)(relu)
template <int C, bool BIAS, bool RELU, bool OUTH>
__global__ void k_agg(const u64* __restrict__ hs, const float* __restrict__ bias,
                      void* __restrict__ outp, int n) {
    constexpr int L = C / 4;
    int lane = threadIdx.x;
    int node = blockIdx.x * blockDim.y + threadIdx.y;
    if (node >= n) return;
    float di = g_dinv[node];
    float4 sv = h4f(hs[(size_t)node * L + lane]);
    float4 acc = make_float4(sv.x * di, sv.y * di, sv.z * di, sv.w * di);
    int b0 = g_off[node], b1 = g_off[node + 1];
    int j = b0;
    for (; j + 3 < b1; j += 4) {
        int s0 = g_col[j], s1 = g_col[j + 1], s2 = g_col[j + 2], s3 = g_col[j + 3];
        float d0 = g_dinv[s0], d1 = g_dinv[s1], d2 = g_dinv[s2], d3 = g_dinv[s3];
        float4 v0 = h4f(hs[(size_t)s0 * L + lane]);
        float4 v1 = h4f(hs[(size_t)s1 * L + lane]);
        float4 v2 = h4f(hs[(size_t)s2 * L + lane]);
        float4 v3 = h4f(hs[(size_t)s3 * L + lane]);
        acc.x += v0.x * d0 + v1.x * d1 + v2.x * d2 + v3.x * d3;
        acc.y += v0.y * d0 + v1.y * d1 + v2.y * d2 + v3.y * d3;
        acc.z += v0.z * d0 + v1.z * d1 + v2.z * d2 + v3.z * d3;
        acc.w += v0.w * d0 + v1.w * d1 + v2.w * d2 + v3.w * d3;
    }
    for (; j < b1; j++) {
        int s = g_col[j];
        float ds = g_dinv[s];
        float4 v = h4f(hs[(size_t)s * L + lane]);
        acc.x += v.x * ds; acc.y += v.y * ds; acc.z += v.z * ds; acc.w += v.w * ds;
    }
    float4 o = make_float4(acc.x * di, acc.y * di, acc.z * di, acc.w * di);
    if (BIAS) {
        float4 bb = reinterpret_cast<const float4*>(bias)[lane];
        o.x += bb.x; o.y += bb.y; o.z += bb.z; o.w += bb.w;
    }
    if (RELU) {
        o.x = fmaxf(o.x, 0.f); o.y = fmaxf(o.y, 0.f);
        o.z = fmaxf(o.z, 0.f); o.w = fmaxf(o.w, 0.f);
    }
    if (OUTH) reinterpret_cast<u64*>(outp)[(size_t)node * L + lane] = f4h(o);
    else      reinterpret_cast<float4*>(outp)[(size_t)node * L + lane] = o;
}

extern "C" void kernel_launch(void* const* d_in, const int* in_sizes, int n_in,
                              void* d_out, int out_size) {
    const float* x    = (const float*)d_in[0];
    const int*   ei   = (const int*)d_in[1];
    const float* eps  = (const float*)d_in[2];
    const float* W_e1 = (const float*)d_in[3];
    const float* b_e1 = (const float*)d_in[4];
    const float* W_e2 = (const float*)d_in[5];
    const float* b_e2 = (const float*)d_in[6];
    const float* W_mu = (const float*)d_in[7];
    const float* b_mu = (const float*)d_in[8];
    const float* W_lv = (const float*)d_in[9];
    const float* b_lv = (const float*)d_in[10];
    const float* W_d1 = (const float*)d_in[11];
    const float* b_d1 = (const float*)d_in[12];
    const float* W_d2 = (const float*)d_in[13];
    const float* b_d2 = (const float*)d_in[14];

    int N = in_sizes[0] / INC;
    int E = in_sizes[1] / 2;
    const int* src = ei;
    const int* dst = ei + E;

    float* out    = (float*)d_out;
    float* out_d  = out;
    float* out_mu = out + (size_t)N * 128;
    float* out_lv = out_mu + (size_t)N * 64;

    float* bufA; float* bufB;
    cudaGetSymbolAddress((void**)&bufA, g_bufA);
    cudaGetSymbolAddress((void**)&bufB, g_bufB);
    u64* hA = (u64*)bufA;
    u64* hB = (u64*)bufB;

    static cudaStream_t s2 = nullptr;
    static cudaEvent_t evF = nullptr, evJ = nullptr;
    if (!s2) {
        cudaStreamCreateWithFlags(&s2, cudaStreamNonBlocking);
        cudaEventCreateWithFlags(&evF, cudaEventDisableTiming);
        cudaEventCreateWithFlags(&evJ, cudaEventDisableTiming);
    }

    int nbScan = (N + 1023) / 1024;
    int mBlk = (N + 127) / 128;

    // ---- CSR build on side stream (overlaps e1 GEMM) ----
    cudaEventRecord(evF, 0);
    cudaStreamWaitEvent(s2, evF, 0);
    k_count<<<(E + 255) / 256, 256, 0, s2>>>(dst, E);
    k_scanA<<<nbScan, 1024, 0, s2>>>(N);
    k_scanB<<<1, 64, 0, s2>>>(nbScan);
    k_scanC<<<nbScan, 1024, 0, s2>>>(N);
    k_fill<<<(E + 255) / 256, 256, 0, s2>>>(src, dst, E);
    cudaEventRecord(evJ, s2);

    // ---- encoder conv1 GEMM: hs = x@W_e1 -> fp16 hA ----
    k_mma<128, 128, false, false, true, false, false><<<dim3(mBlk, 2), 256>>>(
        x, W_e1, nullptr, nullptr, nullptr, hA, nullptr, N);

    cudaStreamWaitEvent(0, evJ, 0);

    // ---- h1 = relu(Â hs + b_e1) -> fp16 hB ----
    k_agg<128, true, true, true><<<(N + 7) / 8, dim3(32, 8)>>>(hA, b_e1, hB, N);

    // ---- encoder conv2: hs = h1@W_e2 -> fp16 hA ; h2 = Â hs + b_e2 -> fp16 hB ----
    k_mma<128, 64, true, false, true, false, false><<<dim3(mBlk, 1), 256>>>(
        hB, W_e2, nullptr, nullptr, nullptr, hA, nullptr, N);
    k_agg<64, true, false, true><<<(N + 15) / 16, dim3(16, 16)>>>(hA, b_e2, hB, N);

    // ---- mu / logvar (fp32, straight to out slices) ----
    k_mma<64, 128, true, true, false, true, false><<<dim3(mBlk, 2), 256>>>(
        hB, W_mu, W_lv, b_mu, b_lv, out_mu, out_lv, N);

    // ---- z = mu + eps*exp(0.5*lv) -> fp16 hA ----
    k_zh<<<(N * 16 + 255) / 256, 256>>>((const float4*)out_mu, (const float4*)out_lv,
                                        (const float4*)eps, hA, N * 16);

    // ---- decoder conv1 (reordered): t = Â z -> fp16 hB ; d1 = relu(t@W_d1+b) -> fp16 hA ----
    k_agg<64, false, false, true><<<(N + 15) / 16, dim3(16, 16)>>>(hA, nullptr, hB, N);
    k_mma<64, 128, true, false, true, true, true><<<dim3(mBlk, 2), 256>>>(
        hB, W_d1, nullptr, b_d1, nullptr, hA, nullptr, N);

    // ---- decoder conv2: hs = d1@W_d2 -> fp16 hB ; d = Â hs + b_d2 -> fp32 out ----
    k_mma<128, 128, true, false, true, false, false><<<dim3(mBlk, 2), 256>>>(
        hA, W_d2, nullptr, nullptr, nullptr, hB, nullptr, N);
    k_agg<128, true, false, false><<<(N + 7) / 8, dim3(32, 8)>>>(hB, b_d2, out_d, N);
}